// round 14
// baseline (speedup 1.0000x reference)
#include <cuda_runtime.h>
#include <cuda_fp16.h>
#include <mma.h>
#include <cstddef>
#include <cstdint>
#include <math.h>

using namespace nvcuda;

#define BATCH 128

typedef unsigned long long ull;

// ---------------------------------------------------------------------------
// f32x2 packed helpers.
// ---------------------------------------------------------------------------
__device__ __forceinline__ ull pack2(float lo, float hi) {
    ull r;
    asm("mov.b64 %0, {%1, %2};" : "=l"(r) : "f"(lo), "f"(hi));
    return r;
}
__device__ __forceinline__ void unpack2(ull v, float& lo, float& hi) {
    asm("mov.b64 {%0, %1}, %2;" : "=f"(lo), "=f"(hi) : "l"(v));
}
__device__ __forceinline__ ull ffma2(ull a, ull b, ull c) {
    ull d;
    asm("fma.rn.f32x2 %0, %1, %2, %3;" : "=l"(d) : "l"(a), "l"(b), "l"(c));
    return d;
}

// ---------------------------------------------------------------------------
// Scratch (no allocations allowed).
// ---------------------------------------------------------------------------
constexpr size_t N_BUF2 = (size_t)BATCH * 96 * 18 * 18;   // pool1 (padded)
constexpr size_t N_BUF3 = (size_t)BATCH * 256 * 16 * 16;  // conv2 out
constexpr size_t N_BUF4 = (size_t)BATCH * 256 * 10 * 10;  // pool2 (padded)
constexpr size_t N_BUF5 = (size_t)BATCH * 384 * 8 * 8;    // conv3 out
constexpr size_t N_BUF6 = (size_t)BATCH * 256 * 6 * 6;    // pcaps out
constexpr size_t N_U    = (size_t)BATCH * 1152 * 8;
constexpr size_t N_BLOG = (size_t)BATCH * 100 * 1152;     // (fp32 slots; used as half)
constexpr size_t N_C    = (size_t)BATCH * 100 * 1152;
constexpr size_t N_V    = (size_t)BATCH * 100 * 16;
constexpr size_t N_F1   = (size_t)BATCH * 4096;
constexpr size_t N_F2   = (size_t)BATCH * 4096;
constexpr size_t N_PART = (size_t)8 * 128 * 4096;
constexpr size_t N_XHAT = (size_t)BATCH * 100 * 1152 * 16;

constexpr size_t O_BUF2 = 0;
constexpr size_t O_BUF3 = O_BUF2 + N_BUF2;
constexpr size_t O_BUF4 = O_BUF3 + N_BUF3;
constexpr size_t O_BUF5 = O_BUF4 + N_BUF4;
constexpr size_t O_BUF6 = O_BUF5 + N_BUF5;
constexpr size_t O_U    = O_BUF6 + N_BUF6;
constexpr size_t O_BLOG = O_U + N_U;
constexpr size_t O_C    = O_BLOG + N_BLOG;
constexpr size_t O_V    = O_C + N_C;
constexpr size_t O_F1   = O_V + N_V;
constexpr size_t O_F2   = O_F1 + N_F1;
constexpr size_t O_PART = O_F2 + N_F2;
constexpr size_t N_TOTAL = O_PART + N_PART;

__device__ __align__(16) float g_scratch[N_TOTAL];
__device__ __align__(16) __half g_xhat[N_XHAT];

constexpr size_t NW2 = (size_t)(96 * 9 + 16) * 256;
constexpr size_t NW3 = (size_t)(256 * 9 + 16) * 384;
constexpr size_t NWP = (size_t)(384 * 9 + 16) * 256;
__device__ __align__(16) __half g_wh[NW2 + NW3 + NWP];

// ---------------------------------------------------------------------------
// Weight prep: fp32 [OC,CIN,3,3] + bias -> fp16 [CIN*9+16, OC].
// ---------------------------------------------------------------------------
__global__ void prep_wconv_kernel(const float* __restrict__ w,
                                  const float* __restrict__ bias,
                                  __half* __restrict__ out, int CIN_, int OC)
{
    int KT = CIN_ * 9 + 16;
    int idx = blockIdx.x * 256 + threadIdx.x;
    if (idx >= KT * OC) return;
    int oc = idx % OC, k = idx / OC;
    float v;
    if (k < CIN_ * 9) {
        int c = k / 144, j = k % 144;
        int ic = c * 16 + j / 9, tap = j % 9;
        v = w[((size_t)oc * CIN_ + ic) * 9 + tap];
    } else {
        int r = k - CIN_ * 9;
        v = (r == 0) ? bias[oc] : 0.f;
    }
    out[(size_t)k * OC + oc] = __float2half(v);
}

// ---------------------------------------------------------------------------
// WMMA fp16 implicit-GEMM 3x3 conv (vectorized 9-tap im2col P-build).
// ---------------------------------------------------------------------------
template<int CIN, int HINP, int WINP, int WOUT, int HWOUT, int NPX, int NPXV,
         int COB, int COUTF, int TPW, bool RELU, bool GUARD>
__global__ void convwmma_kernel(const float* __restrict__ in,
                                const __half* __restrict__ wch,
                                float* __restrict__ out)
{
    constexpr int NCT = COB / 16;
    constexpr int NCH = CIN / 16;
    constexpr int PLD = 144;

    extern __shared__ __align__(16) char smem_raw[];
    __half* P  = (__half*)smem_raw;
    __half* Ws = P + NPX * PLD;
    float*  Stg = (float*)(Ws + 144 * COB);

    const int tid = threadIdx.x;
    const int wid = tid >> 5;
    const int pxt = blockIdx.x;
    const int oc0 = blockIdx.y * COB;
    const int b   = blockIdx.z;
    const int y0  = pxt * (NPX / WOUT);
    const float* inb = in + (size_t)b * CIN * HINP * WINP;

    wmma::fragment<wmma::accumulator, 16, 16, 16, float> acc[TPW];
    #pragma unroll
    for (int i = 0; i < TPW; i++) wmma::fill_fragment(acc[i], 0.f);

    for (int c = 0; c <= NCH; c++) {
        const bool last = (c == NCH);
        __syncthreads();
        if (!last) {
            const int ic0 = c * 16;
            for (int e = tid; e < NPX * 16; e += 256) {
                int px  = e >> 4;
                int icl = e & 15;
                int y = y0 + px / WOUT;
                int x = px % WOUT;
                __half* dst = P + px * PLD + icl * 9;
                if (!GUARD || px < NPXV) {
                    const float* src =
                        inb + ((size_t)(ic0 + icl) * HINP + y) * WINP + x;
                    #pragma unroll
                    for (int r = 0; r < 3; r++) {
                        float a0 = src[r * WINP + 0];
                        float a1 = src[r * WINP + 1];
                        float a2 = src[r * WINP + 2];
                        dst[r * 3 + 0] = __float2half(a0);
                        dst[r * 3 + 1] = __float2half(a1);
                        dst[r * 3 + 2] = __float2half(a2);
                    }
                } else {
                    #pragma unroll
                    for (int t = 0; t < 9; t++) dst[t] = __float2half(0.f);
                }
            }
        } else {
            for (int e = tid; e < NPX * 16; e += 256) {
                int px = e / 16, j = e % 16;
                P[px * PLD + j] = __float2half(j == 0 ? 1.f : 0.f);
            }
        }
        {
            int nrows = last ? 16 : 144;
            int krow0 = c * 144;
            int total8 = nrows * (COB / 8);
            for (int e = tid; e < total8; e += 256) {
                int r = e / (COB / 8), c8 = e % (COB / 8);
                *(uint4*)(Ws + r * COB + c8 * 8) =
                    *(const uint4*)(wch + (size_t)(krow0 + r) * COUTF + oc0 + c8 * 8);
            }
        }
        __syncthreads();
        int nks = last ? 1 : 9;
        for (int s = 0; s < nks; s++) {
            #pragma unroll
            for (int i = 0; i < TPW; i++) {
                int t = wid * TPW + i, rg = t / NCT, ct = t % NCT;
                wmma::fragment<wmma::matrix_a, 16, 16, 16, __half, wmma::row_major> af;
                wmma::fragment<wmma::matrix_b, 16, 16, 16, __half, wmma::row_major> bf;
                wmma::load_matrix_sync(af, P + rg * 16 * PLD + s * 16, PLD);
                wmma::load_matrix_sync(bf, Ws + s * 16 * COB + ct * 16, COB);
                wmma::mma_sync(acc[i], af, bf, acc[i]);
            }
        }
    }

    if (RELU) {
        #pragma unroll
        for (int i = 0; i < TPW; i++)
            for (int e = 0; e < acc[i].num_elements; e++)
                acc[i].x[e] = fmaxf(acc[i].x[e], 0.f);
    }

    if (!GUARD) {
        #pragma unroll
        for (int i = 0; i < TPW; i++) {
            int t = wid * TPW + i, rg = t / NCT, ct = t % NCT;
            float* dst = out + ((size_t)b * COUTF + oc0 + ct * 16) * HWOUT
                         + pxt * NPX + rg * 16;
            wmma::store_matrix_sync(dst, acc[i], HWOUT, wmma::mem_col_major);
        }
    } else {
        float* mystg = Stg + wid * 256;
        #pragma unroll
        for (int i = 0; i < TPW; i++) {
            int t = wid * TPW + i, rg = t / NCT, ct = t % NCT;
            wmma::store_matrix_sync(mystg, acc[i], 16, wmma::mem_col_major);
            __syncwarp();
            int lane = tid & 31;
            for (int e = lane; e < 256; e += 32) {
                int ii = e % 16, j = e / 16;
                int px = rg * 16 + ii;
                if (px < NPXV)
                    out[((size_t)b * COUTF + oc0 + ct * 16 + j) * HWOUT + px] = mystg[e];
            }
            __syncwarp();
        }
    }
}

// ---------------------------------------------------------------------------
// conv1 + pool1 fused: 3->96 conv (relu) then maxpool 3x3 s2 p1, writing
// padded [96,18,18]. Block owns 8 ocs x full 32x32 plane; conv results are
// staged in smem (reusing the input-tile region after compute) then pooled.
// ---------------------------------------------------------------------------
__global__ void conv1_pool_kernel(const float* __restrict__ in,
                                  const float* __restrict__ wt,
                                  const float* __restrict__ bias,
                                  float* __restrict__ out)
{
    // tile: 3 x 34 x 35 ull = 28560B ; psm: 8*32*33 floats = 33792B (union)
    __shared__ __align__(16) char sm[8 * 32 * 33 * 4];
    __shared__ __align__(16) float w_s[3 * 9 * 8];
    ull*   in_s2 = (ull*)sm;
    float* psm   = (float*)sm;

    const int tid   = threadIdx.x;
    const int ocblk = blockIdx.x;   // 12 blocks of 8 oc
    const int b     = blockIdx.y;
    const int oc0   = ocblk * 8;

    const int row  = tid / 8;          // PPT=4: 8 col-groups of 4
    const int col0 = (tid % 8) * 4;

    // load input tile (3 x 34 x 35, zero padded)
    for (int idx = tid; idx < 3 * 34 * 34; idx += 256) {
        int x  = idx % 34;
        int y  = (idx / 34) % 34;
        int ic = idx / (34 * 34);
        int gy = y - 1, gx = x - 1;
        float v = 0.f;
        if (gy >= 0 && gy < 32 && gx >= 0 && gx < 32)
            v = in[((size_t)(b * 3 + ic) * 32 + gy) * 32 + gx];
        in_s2[(ic * 34 + y) * 35 + x] = pack2(v, v);
    }
    for (int idx = tid; idx < 3 * 9 * 8; idx += 256) {
        int oc_l = idx % 8;
        int tap  = (idx / 8) % 9;
        int ic   = idx / 72;
        w_s[(ic * 9 + tap) * 8 + oc_l] =
            wt[((size_t)(oc0 + oc_l) * 3 + ic) * 9 + tap];
    }
    __syncthreads();

    ull acc2[4][4];
    #pragma unroll
    for (int j4 = 0; j4 < 4; j4++) {
        ull bp = pack2(bias[oc0 + 2 * j4], bias[oc0 + 2 * j4 + 1]);
        #pragma unroll
        for (int p = 0; p < 4; p++) acc2[p][j4] = bp;
    }

    #pragma unroll
    for (int ic = 0; ic < 3; ic++) {
        #pragma unroll
        for (int ky = 0; ky < 3; ky++) {
            ull xq[6];
            #pragma unroll
            for (int q = 0; q < 6; q++)
                xq[q] = in_s2[(ic * 34 + row + ky) * 35 + col0 + q];
            #pragma unroll
            for (int kx = 0; kx < 3; kx++) {
                const ulonglong2* wp = reinterpret_cast<const ulonglong2*>(
                    &w_s[(ic * 9 + ky * 3 + kx) * 8]);
                ulonglong2 wA = wp[0];
                ulonglong2 wB = wp[1];
                #pragma unroll
                for (int p = 0; p < 4; p++) {
                    ull xv = xq[p + kx];
                    acc2[p][0] = ffma2(xv, wA.x, acc2[p][0]);
                    acc2[p][1] = ffma2(xv, wA.y, acc2[p][1]);
                    acc2[p][2] = ffma2(xv, wB.x, acc2[p][2]);
                    acc2[p][3] = ffma2(xv, wB.y, acc2[p][3]);
                }
            }
        }
    }
    __syncthreads();   // all tile reads done; smem is reusable

    // stage relu(conv) into psm[oc][32][33]
    #pragma unroll
    for (int j4 = 0; j4 < 4; j4++) {
        #pragma unroll
        for (int p = 0; p < 4; p++) {
            float lo, hi;
            unpack2(acc2[p][j4], lo, hi);
            psm[(2 * j4) * 1056 + row * 33 + col0 + p]     = fmaxf(lo, 0.f);
            psm[(2 * j4 + 1) * 1056 + row * 33 + col0 + p] = fmaxf(hi, 0.f);
        }
    }
    __syncthreads();

    // pool 32x32 -> 16x16, write padded buf2 interior
    for (int idx = tid; idx < 8 * 256; idx += 256) {
        int ocl = idx >> 8;
        int rem = idx & 255;
        int oy = rem >> 4, ox = rem & 15;
        float m = -1e30f;
        #pragma unroll
        for (int dy = 0; dy < 3; dy++) {
            int y = 2 * oy - 1 + dy;
            if (y < 0 || y >= 32) continue;
            #pragma unroll
            for (int dx = 0; dx < 3; dx++) {
                int x = 2 * ox - 1 + dx;
                if (x < 0 || x >= 32) continue;
                m = fmaxf(m, psm[ocl * 1056 + y * 33 + x]);
            }
        }
        out[((size_t)(b * 96 + oc0 + ocl) * 18 + oy + 1) * 18 + ox + 1] = m;
    }
}

// ---------------------------------------------------------------------------
// MaxPool 3x3 stride 2 pad 1 (padded output).
// ---------------------------------------------------------------------------
template<int C, int HIN, int OUTPAD>
__global__ void maxpool_kernel(const float* __restrict__ in, float* __restrict__ out)
{
    constexpr int HO = HIN / 2;
    int idx = blockIdx.x * blockDim.x + threadIdx.x;
    if (idx >= BATCH * C * HO * HO) return;
    int ox = idx % HO;
    int oy = (idx / HO) % HO;
    int c  = (idx / (HO * HO)) % C;
    int b  = idx / (HO * HO * C);
    const float* p = in + ((size_t)(b * C + c)) * HIN * HIN;
    float m = -1e30f;
    #pragma unroll
    for (int dy = 0; dy < 3; dy++) {
        int y = 2 * oy - 1 + dy;
        if (y < 0 || y >= HIN) continue;
        #pragma unroll
        for (int dx = 0; dx < 3; dx++) {
            int x = 2 * ox - 1 + dx;
            if (x < 0 || x >= HIN) continue;
            m = fmaxf(m, p[y * HIN + x]);
        }
    }
    if (OUTPAD) {
        constexpr int HOP = HO + 2;
        out[((size_t)(b * C + c) * HOP + oy + 1) * HOP + ox + 1] = m;
    } else {
        out[idx] = m;
    }
}

// ---------------------------------------------------------------------------
// Squash primarycaps: p flat [B,9216] -> u [B,1152,8]
// ---------------------------------------------------------------------------
__global__ void squash_u_kernel(const float* __restrict__ p, float* __restrict__ u)
{
    int cap = blockIdx.x * blockDim.x + threadIdx.x;
    if (cap >= BATCH * 1152) return;
    const float4* s = reinterpret_cast<const float4*>(p + (size_t)cap * 8);
    float4 a = s[0], b4 = s[1];
    float n2 = a.x * a.x + a.y * a.y + a.z * a.z + a.w * a.w +
               b4.x * b4.x + b4.y * b4.y + b4.z * b4.z + b4.w * b4.w;
    float sc = (n2 / (1.f + n2)) * rsqrtf(n2 + 1e-8f);
    float4* o = reinterpret_cast<float4*>(u + (size_t)cap * 8);
    o[0] = make_float4(a.x * sc, a.y * sc, a.z * sc, a.w * sc);
    o[1] = make_float4(b4.x * sc, b4.y * sc, b4.z * sc, b4.w * sc);
}

// ---------------------------------------------------------------------------
// x_hat fp16; b tiled by 16 (2 syncs per 16 b instead of per b).
// ---------------------------------------------------------------------------
__global__ void xhat16_kernel(const float* __restrict__ Wc,
                              const float* __restrict__ u,
                              __half* __restrict__ xh)
{
    __shared__ float u_s[16 * 256];
    const int o  = blockIdx.y;
    const int i0 = blockIdx.x * 32;
    const int tid = threadIdx.x;
    const int il  = tid >> 3;
    const int dp  = tid & 7;

    const float4* wg4 = reinterpret_cast<const float4*>(
        Wc + (((size_t)o * 1152 + i0 + il) * 16 + dp * 2) * 8);
    float4 w0 = wg4[0], w1 = wg4[1], w2 = wg4[2], w3 = wg4[3];
    float wA[8] = {w0.x, w0.y, w0.z, w0.w, w1.x, w1.y, w1.z, w1.w};
    float wB[8] = {w2.x, w2.y, w2.z, w2.w, w3.x, w3.y, w3.z, w3.w};

    for (int b0 = 0; b0 < BATCH; b0 += 16) {
        __syncthreads();
        #pragma unroll
        for (int bb = 0; bb < 16; bb++)
            u_s[bb * 256 + tid] =
                u[((size_t)(b0 + bb) * 1152 + i0) * 8 + tid];
        __syncthreads();
        #pragma unroll 4
        for (int bb = 0; bb < 16; bb++) {
            const float* ur = &u_s[bb * 256 + il * 8];
            float a0 = 0.f, a1 = 0.f;
            #pragma unroll
            for (int e = 0; e < 8; e++) {
                a0 = fmaf(wA[e], ur[e], a0);
                a1 = fmaf(wB[e], ur[e], a1);
            }
            *reinterpret_cast<__half2*>(
                xh + (((size_t)(b0 + bb) * 100 + o) * 1152 + i0 + il) * 16 + dp * 2) =
                __floats2half2_rn(a0, a1);
        }
    }
}

// ---------------------------------------------------------------------------
// Routing iteration (MODE 0: uniform c, write blog; MODE 1: c from softmax,
// blog +=). s-phase computed from registers during slab staging; warp
// butterfly reduction (full-warp shuffles only). blog/c are fp16.
// ---------------------------------------------------------------------------
template<int MODE>
__global__ void route_fused_kernel(const __half* __restrict__ xhat,
                                   const __half* __restrict__ c,
                                   __half* __restrict__ blog)
{
    __shared__ __align__(16) __half xs[1152 * 16];
    __shared__ float cs[1152];
    __shared__ float stage[8][2][8];
    __shared__ float ss[16];
    __shared__ float vs[16];

    const int o = blockIdx.x, b = blockIdx.y, tid = threadIdx.x;
    const size_t base = (size_t)(b * 100 + o);

    if (MODE != 0) {
        const __half* cg = c + base * 1152;
        for (int i = tid; i < 1152; i += 256) cs[i] = __half2float(cg[i]);
    }
    __syncthreads();

    // stage slab + accumulate partial s in registers
    const float4* xg = reinterpret_cast<const float4*>(xhat + base * 1152 * 16);
    float4* xs4 = reinterpret_cast<float4*>(xs);
    float acc8[8];
    #pragma unroll
    for (int q = 0; q < 8; q++) acc8[q] = 0.f;
    #pragma unroll
    for (int k = 0; k < 9; k++) {
        float4 xv = xg[tid + k * 256];
        xs4[tid + k * 256] = xv;
        int i = (tid >> 1) + k * 128;
        float cc = (MODE == 0) ? 1.f : cs[i];
        const __half2* h = reinterpret_cast<const __half2*>(&xv);
        #pragma unroll
        for (int q = 0; q < 4; q++) {
            float2 f = __half22float2(h[q]);
            acc8[2 * q]     = fmaf(cc, f.x, acc8[2 * q]);
            acc8[2 * q + 1] = fmaf(cc, f.y, acc8[2 * q + 1]);
        }
    }
    // butterfly over j-bits within warp (full-warp shuffles)
    #pragma unroll
    for (int st = 2; st < 32; st <<= 1)
        #pragma unroll
        for (int q = 0; q < 8; q++)
            acc8[q] += __shfl_xor_sync(0xffffffffu, acc8[q], st);
    const int lane = tid & 31, wid = tid >> 5;
    if (lane < 2) {
        #pragma unroll
        for (int q = 0; q < 8; q++) stage[wid][lane][q] = acc8[q];
    }
    __syncthreads();   // also makes xs visible for blog phase
    if (tid < 16) {
        int pp = tid >> 3, d = tid & 7;
        float s = 0.f;
        #pragma unroll
        for (int w = 0; w < 8; w++) s += stage[w][pp][d];
        if (MODE == 0) s *= 0.01f;
        ss[pp * 8 + d] = s;
    }
    __syncthreads();
    if (tid < 16) {
        float n2 = 0.f;
        #pragma unroll
        for (int q = 0; q < 16; q++) n2 += ss[q] * ss[q];
        float sc = (n2 / (1.f + n2)) * rsqrtf(n2 + 1e-8f);
        vs[tid] = ss[tid] * sc;
    }
    __syncthreads();

    // blog[i] (+)= sum_d xhat[i][d] * v[d]
    __half* bl = blog + base * 1152;
    for (int i = tid; i < 1152; i += 256) {
        const float4* xp = reinterpret_cast<const float4*>(xs + i * 16);
        float4 p0 = xp[0], p1 = xp[1];
        const __half2* h0 = reinterpret_cast<const __half2*>(&p0);
        const __half2* h1 = reinterpret_cast<const __half2*>(&p1);
        float dot = 0.f;
        #pragma unroll
        for (int q = 0; q < 4; q++) {
            float2 f = __half22float2(h0[q]);
            dot = fmaf(f.x, vs[q * 2 + 0], dot);
            dot = fmaf(f.y, vs[q * 2 + 1], dot);
        }
        #pragma unroll
        for (int q = 0; q < 4; q++) {
            float2 f = __half22float2(h1[q]);
            dot = fmaf(f.x, vs[8 + q * 2 + 0], dot);
            dot = fmaf(f.y, vs[8 + q * 2 + 1], dot);
        }
        if (MODE == 0) bl[i] = __float2half(dot);
        else           bl[i] = __float2half(__half2float(bl[i]) + dot);
    }
}

// ---------------------------------------------------------------------------
// Final routing iteration: s only, streamed from gmem (no slab staging).
// ---------------------------------------------------------------------------
__global__ void route_final_kernel(const __half* __restrict__ xhat,
                                   const __half* __restrict__ c,
                                   float* __restrict__ v)
{
    __shared__ float cs[1152];
    __shared__ float stage[8][2][8];
    __shared__ float ss[16];

    const int o = blockIdx.x, b = blockIdx.y, tid = threadIdx.x;
    const size_t base = (size_t)(b * 100 + o);

    const __half* cg = c + base * 1152;
    for (int i = tid; i < 1152; i += 256) cs[i] = __half2float(cg[i]);
    __syncthreads();

    const float4* xg = reinterpret_cast<const float4*>(xhat + base * 1152 * 16);
    float acc8[8];
    #pragma unroll
    for (int q = 0; q < 8; q++) acc8[q] = 0.f;
    #pragma unroll
    for (int k = 0; k < 9; k++) {
        float4 xv = xg[tid + k * 256];
        int i = (tid >> 1) + k * 128;
        float cc = cs[i];
        const __half2* h = reinterpret_cast<const __half2*>(&xv);
        #pragma unroll
        for (int q = 0; q < 4; q++) {
            float2 f = __half22float2(h[q]);
            acc8[2 * q]     = fmaf(cc, f.x, acc8[2 * q]);
            acc8[2 * q + 1] = fmaf(cc, f.y, acc8[2 * q + 1]);
        }
    }
    #pragma unroll
    for (int st = 2; st < 32; st <<= 1)
        #pragma unroll
        for (int q = 0; q < 8; q++)
            acc8[q] += __shfl_xor_sync(0xffffffffu, acc8[q], st);
    const int lane = tid & 31, wid = tid >> 5;
    if (lane < 2) {
        #pragma unroll
        for (int q = 0; q < 8; q++) stage[wid][lane][q] = acc8[q];
    }
    __syncthreads();
    if (tid < 16) {
        int pp = tid >> 3, d = tid & 7;
        float s = 0.f;
        #pragma unroll
        for (int w = 0; w < 8; w++) s += stage[w][pp][d];
        ss[pp * 8 + d] = s;
    }
    __syncthreads();
    if (tid < 16) {
        float n2 = 0.f;
        #pragma unroll
        for (int q = 0; q < 16; q++) n2 += ss[q] * ss[q];
        float sc = (n2 / (1.f + n2)) * rsqrtf(n2 + 1e-8f);
        v[base * 16 + tid] = ss[tid] * sc;
    }
}

// ---------------------------------------------------------------------------
// Softmax over o per (b,i): 4-way segmented; fp16 blog/c.
// ---------------------------------------------------------------------------
__global__ void softmax_o_kernel(const __half* __restrict__ blog,
                                 __half* __restrict__ c)
{
    __shared__ float t[100][33];
    __shared__ float red4[4][33];
    __shared__ float sum4[4][33];
    int i0 = blockIdx.x * 32, b = blockIdx.y, tid = threadIdx.x;
    for (int idx = tid; idx < 100 * 32; idx += 128) {
        int ii = idx % 32, o = idx / 32;
        t[o][ii] = __half2float(blog[((size_t)(b * 100 + o)) * 1152 + i0 + ii]);
    }
    __syncthreads();
    int ii = tid & 31, seg = tid >> 5;
    int o0 = seg * 25, o1 = o0 + 25;
    float mx = -1e30f;
    for (int o = o0; o < o1; o++) mx = fmaxf(mx, t[o][ii]);
    red4[seg][ii] = mx;
    __syncthreads();
    float m4 = fmaxf(fmaxf(red4[0][ii], red4[1][ii]),
                     fmaxf(red4[2][ii], red4[3][ii]));
    float sm = 0.f;
    for (int o = o0; o < o1; o++) {
        float e = expf(t[o][ii] - m4);
        t[o][ii] = e;
        sm += e;
    }
    sum4[seg][ii] = sm;
    __syncthreads();
    float inv = 1.f / (sum4[0][ii] + sum4[1][ii] + sum4[2][ii] + sum4[3][ii]);
    for (int o = o0; o < o1; o++) t[o][ii] *= inv;
    __syncthreads();
    for (int idx = tid; idx < 100 * 32; idx += 128) {
        int i2 = idx % 32, o = idx / 32;
        c[((size_t)(b * 100 + o)) * 1152 + i0 + i2] = __float2half(t[o][i2]);
    }
}

// ---------------------------------------------------------------------------
// FC split-K partial GEMM (packed f32x2) + reduce.
// ---------------------------------------------------------------------------
__global__ void fc_part_kernel(const float* __restrict__ A,
                               const float* __restrict__ Wm,
                               float* __restrict__ part,
                               int K_, int N, int kch)
{
    __shared__ __align__(16) ull As2[16][66];
    __shared__ __align__(16) float Bs[16][68];
    int tid = threadIdx.x;
    int n0 = blockIdx.x * 64, m0 = blockIdx.y * 64;
    int kbase = blockIdx.z * kch;
    int tx = tid % 16, ty = tid / 16;
    ull acc2[4][2];
    #pragma unroll
    for (int i = 0; i < 4; i++)
        #pragma unroll
        for (int j = 0; j < 2; j++) acc2[i][j] = 0ull;

    for (int k0 = kbase; k0 < kbase + kch; k0 += 16) {
        #pragma unroll
        for (int rep = 0; rep < 4; rep++) {
            int idx = tid + rep * 256;
            int b_l = idx / 16, k_l = idx % 16;
            float a = A[(size_t)(m0 + b_l) * K_ + k0 + k_l];
            As2[k_l][b_l] = pack2(a, a);
        }
        #pragma unroll
        for (int rep = 0; rep < 4; rep++) {
            int idx = tid + rep * 256;
            int k_l = idx / 64, n_l = idx % 64;
            int n = n0 + n_l;
            Bs[k_l][n_l] = (n < N) ? Wm[(size_t)(k0 + k_l) * N + n] : 0.f;
        }
        __syncthreads();
        #pragma unroll
        for (int k = 0; k < 16; k++) {
            const ulonglong2* bp = reinterpret_cast<const ulonglong2*>(&Bs[k][tx * 4]);
            ulonglong2 bb = bp[0];
            ull a0 = As2[k][ty * 4 + 0];
            ull a1 = As2[k][ty * 4 + 1];
            ull a2 = As2[k][ty * 4 + 2];
            ull a3 = As2[k][ty * 4 + 3];
            acc2[0][0] = ffma2(a0, bb.x, acc2[0][0]);
            acc2[0][1] = ffma2(a0, bb.y, acc2[0][1]);
            acc2[1][0] = ffma2(a1, bb.x, acc2[1][0]);
            acc2[1][1] = ffma2(a1, bb.y, acc2[1][1]);
            acc2[2][0] = ffma2(a2, bb.x, acc2[2][0]);
            acc2[2][1] = ffma2(a2, bb.y, acc2[2][1]);
            acc2[3][0] = ffma2(a3, bb.x, acc2[3][0]);
            acc2[3][1] = ffma2(a3, bb.y, acc2[3][1]);
        }
        __syncthreads();
    }
    float* pz = part + (size_t)blockIdx.z * 128 * N;
    #pragma unroll
    for (int i = 0; i < 4; i++) {
        int m = m0 + ty * 4 + i;
        #pragma unroll
        for (int j = 0; j < 2; j++) {
            float lo, hi;
            unpack2(acc2[i][j], lo, hi);
            int n_lo = n0 + tx * 4 + 2 * j;
            int n_hi = n_lo + 1;
            if (n_lo < N) pz[(size_t)m * N + n_lo] = lo;
            if (n_hi < N) pz[(size_t)m * N + n_hi] = hi;
        }
    }
}

template<bool RELU>
__global__ void fc_reduce_kernel(const float* __restrict__ part,
                                 const float* __restrict__ bias,
                                 float* __restrict__ C, int N, int ksplit)
{
    int idx = blockIdx.x * 256 + threadIdx.x;
    if (idx >= 128 * N) return;
    int n = idx % N, m = idx / N;
    float s = bias[n];
    for (int q = 0; q < ksplit; q++)
        s += part[((size_t)q * 128 + m) * N + n];
    if (RELU) s = fmaxf(s, 0.f);
    C[idx] = s;
}

// ---------------------------------------------------------------------------
// launch
// ---------------------------------------------------------------------------
extern "C" void kernel_launch(void* const* d_in, const int* in_sizes, int n_in,
                              void* d_out, int out_size)
{
    const float* x     = (const float*)d_in[0];
    const float* cw1   = (const float*)d_in[1];
    const float* cb1   = (const float*)d_in[2];
    const float* cw2   = (const float*)d_in[3];
    const float* cb2   = (const float*)d_in[4];
    const float* cw3   = (const float*)d_in[5];
    const float* cb3   = (const float*)d_in[6];
    const float* pw    = (const float*)d_in[7];
    const float* pb    = (const float*)d_in[8];
    const float* Wcaps = (const float*)d_in[9];
    const float* fw1   = (const float*)d_in[10];
    const float* fb1   = (const float*)d_in[11];
    const float* fw2   = (const float*)d_in[12];
    const float* fb2   = (const float*)d_in[13];
    const float* fw3   = (const float*)d_in[14];
    const float* fb3   = (const float*)d_in[15];

    void* sp = nullptr;
    cudaGetSymbolAddress(&sp, g_scratch);
    float* S = (float*)sp;
    void* xp = nullptr;
    cudaGetSymbolAddress(&xp, g_xhat);
    __half* xhat = (__half*)xp;
    void* wp_ = nullptr;
    cudaGetSymbolAddress(&wp_, g_wh);
    __half* w2h = (__half*)wp_;
    __half* w3h = w2h + NW2;
    __half* wph = w3h + NW3;

    float* buf2 = S + O_BUF2;   // padded [96,18,18]
    float* buf3 = S + O_BUF3;
    float* buf4 = S + O_BUF4;   // padded [256,10,10]
    float* buf5 = S + O_BUF5;
    float* buf6 = S + O_BUF6;
    float* u    = S + O_U;
    __half* blogh = (__half*)(S + O_BLOG);
    __half* ch    = (__half*)(S + O_C);
    float* v    = S + O_V;
    float* f1   = S + O_F1;
    float* f2   = S + O_F2;
    float* partb = S + O_PART;
    float* outp = (float*)d_out;

    cudaMemsetAsync(buf2, 0, N_BUF2 * sizeof(float));
    cudaMemsetAsync(buf4, 0, N_BUF4 * sizeof(float));

    prep_wconv_kernel<<<(int)((NW2 + 255) / 256), 256>>>(cw2, cb2, w2h, 96, 256);
    prep_wconv_kernel<<<(int)((NW3 + 255) / 256), 256>>>(cw3, cb3, w3h, 256, 384);
    prep_wconv_kernel<<<(int)((NWP + 255) / 256), 256>>>(pw, pb, wph, 384, 256);

    // conv1 + pool1 fused -> buf2 (padded)
    conv1_pool_kernel<<<dim3(12, BATCH), 256>>>(x, cw1, cb1, buf2);

    // conv2 wmma: in [96,18,18] -> out [256,256]
    {
        constexpr int SM2 = (64 * 144 + 144 * 256) * 2;
        auto kfn = convwmma_kernel<96, 18, 18, 16, 256, 64, 64, 256, 256, 8, true, false>;
        cudaFuncSetAttribute(kfn, cudaFuncAttributeMaxDynamicSharedMemorySize, SM2);
        kfn<<<dim3(4, 1, BATCH), 256, SM2>>>(buf2, w2h, buf3);
    }
    maxpool_kernel<256, 16, 1><<<(BATCH * 256 * 8 * 8 + 255) / 256, 256>>>(buf3, buf4);

    // conv3 wmma: in [256,10,10] -> out [384,64], oc split 2x192
    {
        constexpr int SM3 = (64 * 144 + 144 * 192) * 2;
        auto kfn = convwmma_kernel<256, 10, 10, 8, 64, 64, 64, 192, 384, 6, true, false>;
        cudaFuncSetAttribute(kfn, cudaFuncAttributeMaxDynamicSharedMemorySize, SM3);
        kfn<<<dim3(1, 2, BATCH), 256, SM3>>>(buf4, w3h, buf5);
    }

    // pcaps wmma: in [384,8,8] -> out [256,36], oc split 2x128, px guard 36/48
    {
        constexpr int SMP = (48 * 144 + 144 * 128) * 2 + 8 * 256 * 4;
        auto kfn = convwmma_kernel<384, 8, 8, 6, 36, 48, 36, 128, 256, 3, false, true>;
        cudaFuncSetAttribute(kfn, cudaFuncAttributeMaxDynamicSharedMemorySize, SMP);
        kfn<<<dim3(1, 2, BATCH), 256, SMP>>>(buf5, wph, buf6);
    }

    squash_u_kernel<<<(BATCH * 1152 + 255) / 256, 256>>>(buf6, u);

    // xhat (fp16)
    xhat16_kernel<<<dim3(36, 100), 256>>>(Wcaps, u, xhat);

    // routing
    route_fused_kernel<0><<<dim3(100, BATCH), 256>>>(xhat, ch, blogh);
    softmax_o_kernel<<<dim3(36, BATCH), 128>>>(blogh, ch);
    route_fused_kernel<1><<<dim3(100, BATCH), 256>>>(xhat, ch, blogh);
    softmax_o_kernel<<<dim3(36, BATCH), 128>>>(blogh, ch);
    route_final_kernel<<<dim3(100, BATCH), 256>>>(xhat, ch, v);

    // FC head (split-K + reduce)
    fc_part_kernel<<<dim3(64, 2, 4), 256>>>(v, fw1, partb, 1600, 4096, 400);
    fc_reduce_kernel<true><<<(128 * 4096 + 255) / 256, 256>>>(partb, fb1, f1, 4096, 4);
    fc_part_kernel<<<dim3(64, 2, 8), 256>>>(f1, fw2, partb, 4096, 4096, 512);
    fc_reduce_kernel<true><<<(128 * 4096 + 255) / 256, 256>>>(partb, fb2, f2, 4096, 8);
    fc_part_kernel<<<dim3(2, 2, 32), 256>>>(f2, fw3, partb, 4096, 100, 128);
    fc_reduce_kernel<false><<<(128 * 100 + 255) / 256, 256>>>(partb, fb3, outp, 100, 32);

    (void)in_sizes; (void)n_in; (void)out_size;
}

// round 15
// speedup vs baseline: 1.4240x; 1.4240x over previous
#include <cuda_runtime.h>
#include <cuda_fp16.h>
#include <mma.h>
#include <cstddef>
#include <cstdint>
#include <math.h>

using namespace nvcuda;

#define BATCH 128

typedef unsigned long long ull;

// ---------------------------------------------------------------------------
// f32x2 packed helpers.
// ---------------------------------------------------------------------------
__device__ __forceinline__ ull pack2(float lo, float hi) {
    ull r;
    asm("mov.b64 %0, {%1, %2};" : "=l"(r) : "f"(lo), "f"(hi));
    return r;
}
__device__ __forceinline__ void unpack2(ull v, float& lo, float& hi) {
    asm("mov.b64 {%0, %1}, %2;" : "=f"(lo), "=f"(hi) : "l"(v));
}
__device__ __forceinline__ ull ffma2(ull a, ull b, ull c) {
    ull d;
    asm("fma.rn.f32x2 %0, %1, %2, %3;" : "=l"(d) : "l"(a), "l"(b), "l"(c));
    return d;
}

// ---------------------------------------------------------------------------
// Scratch (no allocations allowed).
// ---------------------------------------------------------------------------
constexpr size_t N_BUF2 = (size_t)BATCH * 96 * 18 * 18;   // pool1 (padded)
constexpr size_t N_BUF3 = (size_t)BATCH * 256 * 16 * 16;  // conv2 out
constexpr size_t N_BUF4 = (size_t)BATCH * 256 * 10 * 10;  // pool2 (padded)
constexpr size_t N_BUF5 = (size_t)BATCH * 384 * 8 * 8;    // conv3 out
constexpr size_t N_BUF6 = (size_t)BATCH * 256 * 6 * 6;    // pcaps out
constexpr size_t N_U    = (size_t)BATCH * 1152 * 8;
constexpr size_t N_BLOG = (size_t)BATCH * 100 * 1152;
constexpr size_t N_C    = (size_t)BATCH * 100 * 1152;
constexpr size_t N_V    = (size_t)BATCH * 100 * 16;
constexpr size_t N_F1   = (size_t)BATCH * 4096;
constexpr size_t N_F2   = (size_t)BATCH * 4096;
constexpr size_t N_PART = (size_t)8 * 128 * 4096;
constexpr size_t N_XHAT = (size_t)BATCH * 100 * 1152 * 16;

constexpr size_t O_BUF2 = 0;
constexpr size_t O_BUF3 = O_BUF2 + N_BUF2;
constexpr size_t O_BUF4 = O_BUF3 + N_BUF3;
constexpr size_t O_BUF5 = O_BUF4 + N_BUF4;
constexpr size_t O_BUF6 = O_BUF5 + N_BUF5;
constexpr size_t O_U    = O_BUF6 + N_BUF6;
constexpr size_t O_BLOG = O_U + N_U;
constexpr size_t O_C    = O_BLOG + N_BLOG;
constexpr size_t O_V    = O_C + N_C;
constexpr size_t O_F1   = O_V + N_V;
constexpr size_t O_F2   = O_F1 + N_F1;
constexpr size_t O_PART = O_F2 + N_F2;
constexpr size_t N_TOTAL = O_PART + N_PART;

__device__ __align__(16) float g_scratch[N_TOTAL];
__device__ __align__(16) __half g_xhat[N_XHAT];

constexpr size_t NW2 = (size_t)(96 * 9 + 16) * 256;
constexpr size_t NW3 = (size_t)(256 * 9 + 16) * 384;
constexpr size_t NWP = (size_t)(384 * 9 + 16) * 256;
__device__ __align__(16) __half g_wh[NW2 + NW3 + NWP];

// ---------------------------------------------------------------------------
// Weight prep: fp32 [OC,CIN,3,3] + bias -> fp16 [CIN*9+16, OC].
// ---------------------------------------------------------------------------
__global__ void prep_wconv_kernel(const float* __restrict__ w,
                                  const float* __restrict__ bias,
                                  __half* __restrict__ out, int CIN_, int OC)
{
    int KT = CIN_ * 9 + 16;
    int idx = blockIdx.x * 256 + threadIdx.x;
    if (idx >= KT * OC) return;
    int oc = idx % OC, k = idx / OC;
    float v;
    if (k < CIN_ * 9) {
        int c = k / 144, j = k % 144;
        int ic = c * 16 + j / 9, tap = j % 9;
        v = w[((size_t)oc * CIN_ + ic) * 9 + tap];
    } else {
        int r = k - CIN_ * 9;
        v = (r == 0) ? bias[oc] : 0.f;
    }
    out[(size_t)k * OC + oc] = __float2half(v);
}

// ---------------------------------------------------------------------------
// WMMA fp16 implicit-GEMM 3x3 conv (vectorized 9-tap im2col P-build).
// ---------------------------------------------------------------------------
template<int CIN, int HINP, int WINP, int WOUT, int HWOUT, int NPX, int NPXV,
         int COB, int COUTF, int TPW, bool RELU, bool GUARD>
__global__ void convwmma_kernel(const float* __restrict__ in,
                                const __half* __restrict__ wch,
                                float* __restrict__ out)
{
    constexpr int NCT = COB / 16;
    constexpr int NCH = CIN / 16;
    constexpr int PLD = 144;

    extern __shared__ __align__(16) char smem_raw[];
    __half* P  = (__half*)smem_raw;
    __half* Ws = P + NPX * PLD;
    float*  Stg = (float*)(Ws + 144 * COB);

    const int tid = threadIdx.x;
    const int wid = tid >> 5;
    const int pxt = blockIdx.x;
    const int oc0 = blockIdx.y * COB;
    const int b   = blockIdx.z;
    const int y0  = pxt * (NPX / WOUT);
    const float* inb = in + (size_t)b * CIN * HINP * WINP;

    wmma::fragment<wmma::accumulator, 16, 16, 16, float> acc[TPW];
    #pragma unroll
    for (int i = 0; i < TPW; i++) wmma::fill_fragment(acc[i], 0.f);

    for (int c = 0; c <= NCH; c++) {
        const bool last = (c == NCH);
        __syncthreads();
        if (!last) {
            const int ic0 = c * 16;
            for (int e = tid; e < NPX * 16; e += 256) {
                int px  = e >> 4;
                int icl = e & 15;
                int y = y0 + px / WOUT;
                int x = px % WOUT;
                __half* dst = P + px * PLD + icl * 9;
                if (!GUARD || px < NPXV) {
                    const float* src =
                        inb + ((size_t)(ic0 + icl) * HINP + y) * WINP + x;
                    #pragma unroll
                    for (int r = 0; r < 3; r++) {
                        float a0 = src[r * WINP + 0];
                        float a1 = src[r * WINP + 1];
                        float a2 = src[r * WINP + 2];
                        dst[r * 3 + 0] = __float2half(a0);
                        dst[r * 3 + 1] = __float2half(a1);
                        dst[r * 3 + 2] = __float2half(a2);
                    }
                } else {
                    #pragma unroll
                    for (int t = 0; t < 9; t++) dst[t] = __float2half(0.f);
                }
            }
        } else {
            for (int e = tid; e < NPX * 16; e += 256) {
                int px = e / 16, j = e % 16;
                P[px * PLD + j] = __float2half(j == 0 ? 1.f : 0.f);
            }
        }
        {
            int nrows = last ? 16 : 144;
            int krow0 = c * 144;
            int total8 = nrows * (COB / 8);
            for (int e = tid; e < total8; e += 256) {
                int r = e / (COB / 8), c8 = e % (COB / 8);
                *(uint4*)(Ws + r * COB + c8 * 8) =
                    *(const uint4*)(wch + (size_t)(krow0 + r) * COUTF + oc0 + c8 * 8);
            }
        }
        __syncthreads();
        int nks = last ? 1 : 9;
        for (int s = 0; s < nks; s++) {
            #pragma unroll
            for (int i = 0; i < TPW; i++) {
                int t = wid * TPW + i, rg = t / NCT, ct = t % NCT;
                wmma::fragment<wmma::matrix_a, 16, 16, 16, __half, wmma::row_major> af;
                wmma::fragment<wmma::matrix_b, 16, 16, 16, __half, wmma::row_major> bf;
                wmma::load_matrix_sync(af, P + rg * 16 * PLD + s * 16, PLD);
                wmma::load_matrix_sync(bf, Ws + s * 16 * COB + ct * 16, COB);
                wmma::mma_sync(acc[i], af, bf, acc[i]);
            }
        }
    }

    if (RELU) {
        #pragma unroll
        for (int i = 0; i < TPW; i++)
            for (int e = 0; e < acc[i].num_elements; e++)
                acc[i].x[e] = fmaxf(acc[i].x[e], 0.f);
    }

    if (!GUARD) {
        #pragma unroll
        for (int i = 0; i < TPW; i++) {
            int t = wid * TPW + i, rg = t / NCT, ct = t % NCT;
            float* dst = out + ((size_t)b * COUTF + oc0 + ct * 16) * HWOUT
                         + pxt * NPX + rg * 16;
            wmma::store_matrix_sync(dst, acc[i], HWOUT, wmma::mem_col_major);
        }
    } else {
        float* mystg = Stg + wid * 256;
        #pragma unroll
        for (int i = 0; i < TPW; i++) {
            int t = wid * TPW + i, rg = t / NCT, ct = t % NCT;
            wmma::store_matrix_sync(mystg, acc[i], 16, wmma::mem_col_major);
            __syncwarp();
            int lane = tid & 31;
            for (int e = lane; e < 256; e += 32) {
                int ii = e % 16, j = e / 16;
                int px = rg * 16 + ii;
                if (px < NPXV)
                    out[((size_t)b * COUTF + oc0 + ct * 16 + j) * HWOUT + px] = mystg[e];
            }
            __syncwarp();
        }
    }
}

// ---------------------------------------------------------------------------
// conv1 + pool1 fused (measured win in R14): conv 3->96 relu + maxpool 3x3
// s2 p1, writing padded [96,18,18]. Conv math identical to R13.
// ---------------------------------------------------------------------------
__global__ void conv1_pool_kernel(const float* __restrict__ in,
                                  const float* __restrict__ wt,
                                  const float* __restrict__ bias,
                                  float* __restrict__ out)
{
    __shared__ __align__(16) char sm[8 * 32 * 33 * 4];
    __shared__ __align__(16) float w_s[3 * 9 * 8];
    ull*   in_s2 = (ull*)sm;
    float* psm   = (float*)sm;

    const int tid   = threadIdx.x;
    const int ocblk = blockIdx.x;
    const int b     = blockIdx.y;
    const int oc0   = ocblk * 8;

    const int row  = tid / 8;
    const int col0 = (tid % 8) * 4;

    for (int idx = tid; idx < 3 * 34 * 34; idx += 256) {
        int x  = idx % 34;
        int y  = (idx / 34) % 34;
        int ic = idx / (34 * 34);
        int gy = y - 1, gx = x - 1;
        float v = 0.f;
        if (gy >= 0 && gy < 32 && gx >= 0 && gx < 32)
            v = in[((size_t)(b * 3 + ic) * 32 + gy) * 32 + gx];
        in_s2[(ic * 34 + y) * 35 + x] = pack2(v, v);
    }
    for (int idx = tid; idx < 3 * 9 * 8; idx += 256) {
        int oc_l = idx % 8;
        int tap  = (idx / 8) % 9;
        int ic   = idx / 72;
        w_s[(ic * 9 + tap) * 8 + oc_l] =
            wt[((size_t)(oc0 + oc_l) * 3 + ic) * 9 + tap];
    }
    __syncthreads();

    ull acc2[4][4];
    #pragma unroll
    for (int j4 = 0; j4 < 4; j4++) {
        ull bp = pack2(bias[oc0 + 2 * j4], bias[oc0 + 2 * j4 + 1]);
        #pragma unroll
        for (int p = 0; p < 4; p++) acc2[p][j4] = bp;
    }

    #pragma unroll
    for (int ic = 0; ic < 3; ic++) {
        #pragma unroll
        for (int ky = 0; ky < 3; ky++) {
            ull xq[6];
            #pragma unroll
            for (int q = 0; q < 6; q++)
                xq[q] = in_s2[(ic * 34 + row + ky) * 35 + col0 + q];
            #pragma unroll
            for (int kx = 0; kx < 3; kx++) {
                const ulonglong2* wp = reinterpret_cast<const ulonglong2*>(
                    &w_s[(ic * 9 + ky * 3 + kx) * 8]);
                ulonglong2 wA = wp[0];
                ulonglong2 wB = wp[1];
                #pragma unroll
                for (int p = 0; p < 4; p++) {
                    ull xv = xq[p + kx];
                    acc2[p][0] = ffma2(xv, wA.x, acc2[p][0]);
                    acc2[p][1] = ffma2(xv, wA.y, acc2[p][1]);
                    acc2[p][2] = ffma2(xv, wB.x, acc2[p][2]);
                    acc2[p][3] = ffma2(xv, wB.y, acc2[p][3]);
                }
            }
        }
    }
    __syncthreads();

    #pragma unroll
    for (int j4 = 0; j4 < 4; j4++) {
        #pragma unroll
        for (int p = 0; p < 4; p++) {
            float lo, hi;
            unpack2(acc2[p][j4], lo, hi);
            psm[(2 * j4) * 1056 + row * 33 + col0 + p]     = fmaxf(lo, 0.f);
            psm[(2 * j4 + 1) * 1056 + row * 33 + col0 + p] = fmaxf(hi, 0.f);
        }
    }
    __syncthreads();

    for (int idx = tid; idx < 8 * 256; idx += 256) {
        int ocl = idx >> 8;
        int rem = idx & 255;
        int oy = rem >> 4, ox = rem & 15;
        float m = -1e30f;
        #pragma unroll
        for (int dy = 0; dy < 3; dy++) {
            int y = 2 * oy - 1 + dy;
            if (y < 0 || y >= 32) continue;
            #pragma unroll
            for (int dx = 0; dx < 3; dx++) {
                int x = 2 * ox - 1 + dx;
                if (x < 0 || x >= 32) continue;
                m = fmaxf(m, psm[ocl * 1056 + y * 33 + x]);
            }
        }
        out[((size_t)(b * 96 + oc0 + ocl) * 18 + oy + 1) * 18 + ox + 1] = m;
    }
}

// ---------------------------------------------------------------------------
// MaxPool 3x3 stride 2 pad 1 (padded output) — pool2 only.
// ---------------------------------------------------------------------------
template<int C, int HIN, int OUTPAD>
__global__ void maxpool_kernel(const float* __restrict__ in, float* __restrict__ out)
{
    constexpr int HO = HIN / 2;
    int idx = blockIdx.x * blockDim.x + threadIdx.x;
    if (idx >= BATCH * C * HO * HO) return;
    int ox = idx % HO;
    int oy = (idx / HO) % HO;
    int c  = (idx / (HO * HO)) % C;
    int b  = idx / (HO * HO * C);
    const float* p = in + ((size_t)(b * C + c)) * HIN * HIN;
    float m = -1e30f;
    #pragma unroll
    for (int dy = 0; dy < 3; dy++) {
        int y = 2 * oy - 1 + dy;
        if (y < 0 || y >= HIN) continue;
        #pragma unroll
        for (int dx = 0; dx < 3; dx++) {
            int x = 2 * ox - 1 + dx;
            if (x < 0 || x >= HIN) continue;
            m = fmaxf(m, p[y * HIN + x]);
        }
    }
    if (OUTPAD) {
        constexpr int HOP = HO + 2;
        out[((size_t)(b * C + c) * HOP + oy + 1) * HOP + ox + 1] = m;
    } else {
        out[idx] = m;
    }
}

// ---------------------------------------------------------------------------
// Squash primarycaps: p flat [B,9216] -> u [B,1152,8]
// ---------------------------------------------------------------------------
__global__ void squash_u_kernel(const float* __restrict__ p, float* __restrict__ u)
{
    int cap = blockIdx.x * blockDim.x + threadIdx.x;
    if (cap >= BATCH * 1152) return;
    const float4* s = reinterpret_cast<const float4*>(p + (size_t)cap * 8);
    float4 a = s[0], b4 = s[1];
    float n2 = a.x * a.x + a.y * a.y + a.z * a.z + a.w * a.w +
               b4.x * b4.x + b4.y * b4.y + b4.z * b4.z + b4.w * b4.w;
    float sc = (n2 / (1.f + n2)) * rsqrtf(n2 + 1e-8f);
    float4* o = reinterpret_cast<float4*>(u + (size_t)cap * 8);
    o[0] = make_float4(a.x * sc, a.y * sc, a.z * sc, a.w * sc);
    o[1] = make_float4(b4.x * sc, b4.y * sc, b4.z * sc, b4.w * sc);
}

// ---------------------------------------------------------------------------
// x_hat fp16; b tiled by 16 (2 syncs per 16 b instead of per b).
// ---------------------------------------------------------------------------
__global__ void xhat16_kernel(const float* __restrict__ Wc,
                              const float* __restrict__ u,
                              __half* __restrict__ xh)
{
    __shared__ float u_s[16 * 256];
    const int o  = blockIdx.y;
    const int i0 = blockIdx.x * 32;
    const int tid = threadIdx.x;
    const int il  = tid >> 3;
    const int dp  = tid & 7;

    const float4* wg4 = reinterpret_cast<const float4*>(
        Wc + (((size_t)o * 1152 + i0 + il) * 16 + dp * 2) * 8);
    float4 w0 = wg4[0], w1 = wg4[1], w2 = wg4[2], w3 = wg4[3];
    float wA[8] = {w0.x, w0.y, w0.z, w0.w, w1.x, w1.y, w1.z, w1.w};
    float wB[8] = {w2.x, w2.y, w2.z, w2.w, w3.x, w3.y, w3.z, w3.w};

    for (int b0 = 0; b0 < BATCH; b0 += 16) {
        __syncthreads();
        #pragma unroll
        for (int bb = 0; bb < 16; bb++)
            u_s[bb * 256 + tid] =
                u[((size_t)(b0 + bb) * 1152 + i0) * 8 + tid];
        __syncthreads();
        #pragma unroll 4
        for (int bb = 0; bb < 16; bb++) {
            const float* ur = &u_s[bb * 256 + il * 8];
            float a0 = 0.f, a1 = 0.f;
            #pragma unroll
            for (int e = 0; e < 8; e++) {
                a0 = fmaf(wA[e], ur[e], a0);
                a1 = fmaf(wB[e], ur[e], a1);
            }
            *reinterpret_cast<__half2*>(
                xh + (((size_t)(b0 + bb) * 100 + o) * 1152 + i0 + il) * 16 + dp * 2) =
                __floats2half2_rn(a0, a1);
        }
    }
}

// ---------------------------------------------------------------------------
// Fused routing iteration — EXACT R13 version (smem s-phase; fp32 blog/c).
// ---------------------------------------------------------------------------
template<int MODE>
__global__ void route_fused_kernel(const __half* __restrict__ xhat,
                                   const float* __restrict__ c,
                                   float* __restrict__ blog,
                                   float* __restrict__ v)
{
    __shared__ __align__(16) __half xs[1152 * 16];
    __shared__ float cs[1152];
    __shared__ float red[256];
    __shared__ float vs[16];

    const int o = blockIdx.x, b = blockIdx.y, tid = threadIdx.x;
    const size_t base = (size_t)(b * 100 + o);

    const float4* xg = reinterpret_cast<const float4*>(xhat + base * 1152 * 16);
    float4* xs4 = reinterpret_cast<float4*>(xs);
    #pragma unroll
    for (int k = 0; k < 9; k++) xs4[tid + k * 256] = xg[tid + k * 256];

    if (MODE != 0) {
        const float* cg = c + base * 1152;
        for (int i = tid; i < 1152; i += 256) cs[i] = cg[i];
    }
    __syncthreads();

    const int d = tid & 15, ig = tid >> 4;
    float acc = 0.f;
    for (int i = ig; i < 1152; i += 16) {
        float x = __half2float(xs[i * 16 + d]);
        if (MODE == 0) acc += x;
        else           acc = fmaf(cs[i], x, acc);
    }
    red[tid] = acc;
    __syncthreads();
    #pragma unroll
    for (int st = 128; st >= 16; st >>= 1) {
        if (tid < st) red[tid] += red[tid + st];
        __syncthreads();
    }
    if (tid < 16) {
        float s = red[tid];
        if (MODE == 0) s *= 0.01f;
        red[tid] = s;
    }
    __syncthreads();
    if (tid < 16) {
        float n2 = 0.f;
        #pragma unroll
        for (int q = 0; q < 16; q++) n2 += red[q] * red[q];
        float sc = (n2 / (1.f + n2)) * rsqrtf(n2 + 1e-8f);
        float vv = red[tid] * sc;
        vs[tid] = vv;
        if (MODE == 2) v[base * 16 + tid] = vv;
    }
    if (MODE == 2) return;
    __syncthreads();

    float* bl = blog + base * 1152;
    for (int i = tid; i < 1152; i += 256) {
        const float4* xp = reinterpret_cast<const float4*>(xs + i * 16);
        float4 p0 = xp[0], p1 = xp[1];
        const __half2* h0 = reinterpret_cast<const __half2*>(&p0);
        const __half2* h1 = reinterpret_cast<const __half2*>(&p1);
        float dot = 0.f;
        #pragma unroll
        for (int q = 0; q < 4; q++) {
            float2 f = __half22float2(h0[q]);
            dot = fmaf(f.x, vs[q * 2 + 0], dot);
            dot = fmaf(f.y, vs[q * 2 + 1], dot);
        }
        #pragma unroll
        for (int q = 0; q < 4; q++) {
            float2 f = __half22float2(h1[q]);
            dot = fmaf(f.x, vs[8 + q * 2 + 0], dot);
            dot = fmaf(f.y, vs[8 + q * 2 + 1], dot);
        }
        if (MODE == 0) bl[i] = dot;
        else           bl[i] += dot;
    }
}

// ---------------------------------------------------------------------------
// Softmax over o per (b,i): 4-way segmented (R13 version, fp32).
// ---------------------------------------------------------------------------
__global__ void softmax_o_kernel(const float* __restrict__ blog, float* __restrict__ c)
{
    __shared__ float t[100][33];
    __shared__ float red4[4][33];
    __shared__ float sum4[4][33];
    int i0 = blockIdx.x * 32, b = blockIdx.y, tid = threadIdx.x;
    for (int idx = tid; idx < 100 * 32; idx += 128) {
        int ii = idx % 32, o = idx / 32;
        t[o][ii] = blog[((size_t)(b * 100 + o)) * 1152 + i0 + ii];
    }
    __syncthreads();
    int ii = tid & 31, seg = tid >> 5;
    int o0 = seg * 25, o1 = o0 + 25;
    float mx = -1e30f;
    for (int o = o0; o < o1; o++) mx = fmaxf(mx, t[o][ii]);
    red4[seg][ii] = mx;
    __syncthreads();
    float m4 = fmaxf(fmaxf(red4[0][ii], red4[1][ii]),
                     fmaxf(red4[2][ii], red4[3][ii]));
    float sm = 0.f;
    for (int o = o0; o < o1; o++) {
        float e = expf(t[o][ii] - m4);
        t[o][ii] = e;
        sm += e;
    }
    sum4[seg][ii] = sm;
    __syncthreads();
    float inv = 1.f / (sum4[0][ii] + sum4[1][ii] + sum4[2][ii] + sum4[3][ii]);
    for (int o = o0; o < o1; o++) t[o][ii] *= inv;
    __syncthreads();
    for (int idx = tid; idx < 100 * 32; idx += 128) {
        int i2 = idx % 32, o = idx / 32;
        c[((size_t)(b * 100 + o)) * 1152 + i0 + i2] = t[o][i2];
    }
}

// ---------------------------------------------------------------------------
// FC split-K partial GEMM (packed f32x2) + reduce.
// ---------------------------------------------------------------------------
__global__ void fc_part_kernel(const float* __restrict__ A,
                               const float* __restrict__ Wm,
                               float* __restrict__ part,
                               int K_, int N, int kch)
{
    __shared__ __align__(16) ull As2[16][66];
    __shared__ __align__(16) float Bs[16][68];
    int tid = threadIdx.x;
    int n0 = blockIdx.x * 64, m0 = blockIdx.y * 64;
    int kbase = blockIdx.z * kch;
    int tx = tid % 16, ty = tid / 16;
    ull acc2[4][2];
    #pragma unroll
    for (int i = 0; i < 4; i++)
        #pragma unroll
        for (int j = 0; j < 2; j++) acc2[i][j] = 0ull;

    for (int k0 = kbase; k0 < kbase + kch; k0 += 16) {
        #pragma unroll
        for (int rep = 0; rep < 4; rep++) {
            int idx = tid + rep * 256;
            int b_l = idx / 16, k_l = idx % 16;
            float a = A[(size_t)(m0 + b_l) * K_ + k0 + k_l];
            As2[k_l][b_l] = pack2(a, a);
        }
        #pragma unroll
        for (int rep = 0; rep < 4; rep++) {
            int idx = tid + rep * 256;
            int k_l = idx / 64, n_l = idx % 64;
            int n = n0 + n_l;
            Bs[k_l][n_l] = (n < N) ? Wm[(size_t)(k0 + k_l) * N + n] : 0.f;
        }
        __syncthreads();
        #pragma unroll
        for (int k = 0; k < 16; k++) {
            const ulonglong2* bp = reinterpret_cast<const ulonglong2*>(&Bs[k][tx * 4]);
            ulonglong2 bb = bp[0];
            ull a0 = As2[k][ty * 4 + 0];
            ull a1 = As2[k][ty * 4 + 1];
            ull a2 = As2[k][ty * 4 + 2];
            ull a3 = As2[k][ty * 4 + 3];
            acc2[0][0] = ffma2(a0, bb.x, acc2[0][0]);
            acc2[0][1] = ffma2(a0, bb.y, acc2[0][1]);
            acc2[1][0] = ffma2(a1, bb.x, acc2[1][0]);
            acc2[1][1] = ffma2(a1, bb.y, acc2[1][1]);
            acc2[2][0] = ffma2(a2, bb.x, acc2[2][0]);
            acc2[2][1] = ffma2(a2, bb.y, acc2[2][1]);
            acc2[3][0] = ffma2(a3, bb.x, acc2[3][0]);
            acc2[3][1] = ffma2(a3, bb.y, acc2[3][1]);
        }
        __syncthreads();
    }
    float* pz = part + (size_t)blockIdx.z * 128 * N;
    #pragma unroll
    for (int i = 0; i < 4; i++) {
        int m = m0 + ty * 4 + i;
        #pragma unroll
        for (int j = 0; j < 2; j++) {
            float lo, hi;
            unpack2(acc2[i][j], lo, hi);
            int n_lo = n0 + tx * 4 + 2 * j;
            int n_hi = n_lo + 1;
            if (n_lo < N) pz[(size_t)m * N + n_lo] = lo;
            if (n_hi < N) pz[(size_t)m * N + n_hi] = hi;
        }
    }
}

template<bool RELU>
__global__ void fc_reduce_kernel(const float* __restrict__ part,
                                 const float* __restrict__ bias,
                                 float* __restrict__ C, int N, int ksplit)
{
    int idx = blockIdx.x * 256 + threadIdx.x;
    if (idx >= 128 * N) return;
    int n = idx % N, m = idx / N;
    float s = bias[n];
    for (int q = 0; q < ksplit; q++)
        s += part[((size_t)q * 128 + m) * N + n];
    if (RELU) s = fmaxf(s, 0.f);
    C[idx] = s;
}

// ---------------------------------------------------------------------------
// launch
// ---------------------------------------------------------------------------
extern "C" void kernel_launch(void* const* d_in, const int* in_sizes, int n_in,
                              void* d_out, int out_size)
{
    const float* x     = (const float*)d_in[0];
    const float* cw1   = (const float*)d_in[1];
    const float* cb1   = (const float*)d_in[2];
    const float* cw2   = (const float*)d_in[3];
    const float* cb2   = (const float*)d_in[4];
    const float* cw3   = (const float*)d_in[5];
    const float* cb3   = (const float*)d_in[6];
    const float* pw    = (const float*)d_in[7];
    const float* pb    = (const float*)d_in[8];
    const float* Wcaps = (const float*)d_in[9];
    const float* fw1   = (const float*)d_in[10];
    const float* fb1   = (const float*)d_in[11];
    const float* fw2   = (const float*)d_in[12];
    const float* fb2   = (const float*)d_in[13];
    const float* fw3   = (const float*)d_in[14];
    const float* fb3   = (const float*)d_in[15];

    void* sp = nullptr;
    cudaGetSymbolAddress(&sp, g_scratch);
    float* S = (float*)sp;
    void* xp = nullptr;
    cudaGetSymbolAddress(&xp, g_xhat);
    __half* xhat = (__half*)xp;
    void* wp_ = nullptr;
    cudaGetSymbolAddress(&wp_, g_wh);
    __half* w2h = (__half*)wp_;
    __half* w3h = w2h + NW2;
    __half* wph = w3h + NW3;

    float* buf2 = S + O_BUF2;   // padded [96,18,18]
    float* buf3 = S + O_BUF3;
    float* buf4 = S + O_BUF4;   // padded [256,10,10]
    float* buf5 = S + O_BUF5;
    float* buf6 = S + O_BUF6;
    float* u    = S + O_U;
    float* blog = S + O_BLOG;
    float* cbuf = S + O_C;
    float* v    = S + O_V;
    float* f1   = S + O_F1;
    float* f2   = S + O_F2;
    float* partb = S + O_PART;
    float* outp = (float*)d_out;

    cudaMemsetAsync(buf2, 0, N_BUF2 * sizeof(float));
    cudaMemsetAsync(buf4, 0, N_BUF4 * sizeof(float));

    prep_wconv_kernel<<<(int)((NW2 + 255) / 256), 256>>>(cw2, cb2, w2h, 96, 256);
    prep_wconv_kernel<<<(int)((NW3 + 255) / 256), 256>>>(cw3, cb3, w3h, 256, 384);
    prep_wconv_kernel<<<(int)((NWP + 255) / 256), 256>>>(pw, pb, wph, 384, 256);

    // conv1 + pool1 fused -> buf2 (padded)
    conv1_pool_kernel<<<dim3(12, BATCH), 256>>>(x, cw1, cb1, buf2);

    // conv2 wmma: in [96,18,18] -> out [256,256]
    {
        constexpr int SM2 = (64 * 144 + 144 * 256) * 2;
        auto kfn = convwmma_kernel<96, 18, 18, 16, 256, 64, 64, 256, 256, 8, true, false>;
        cudaFuncSetAttribute(kfn, cudaFuncAttributeMaxDynamicSharedMemorySize, SM2);
        kfn<<<dim3(4, 1, BATCH), 256, SM2>>>(buf2, w2h, buf3);
    }
    maxpool_kernel<256, 16, 1><<<(BATCH * 256 * 8 * 8 + 255) / 256, 256>>>(buf3, buf4);

    // conv3 wmma: in [256,10,10] -> out [384,64], oc split 2x192
    {
        constexpr int SM3 = (64 * 144 + 144 * 192) * 2;
        auto kfn = convwmma_kernel<256, 10, 10, 8, 64, 64, 64, 192, 384, 6, true, false>;
        cudaFuncSetAttribute(kfn, cudaFuncAttributeMaxDynamicSharedMemorySize, SM3);
        kfn<<<dim3(1, 2, BATCH), 256, SM3>>>(buf4, w3h, buf5);
    }

    // pcaps wmma: in [384,8,8] -> out [256,36], oc split 2x128, px guard 36/48
    {
        constexpr int SMP = (48 * 144 + 144 * 128) * 2 + 8 * 256 * 4;
        auto kfn = convwmma_kernel<384, 8, 8, 6, 36, 48, 36, 128, 256, 3, false, true>;
        cudaFuncSetAttribute(kfn, cudaFuncAttributeMaxDynamicSharedMemorySize, SMP);
        kfn<<<dim3(1, 2, BATCH), 256, SMP>>>(buf5, wph, buf6);
    }

    squash_u_kernel<<<(BATCH * 1152 + 255) / 256, 256>>>(buf6, u);

    // xhat (fp16, b-tiled)
    xhat16_kernel<<<dim3(36, 100), 256>>>(Wcaps, u, xhat);

    // routing: 3 fused iterations, softmax between (R13 kernels)
    route_fused_kernel<0><<<dim3(100, BATCH), 256>>>(xhat, cbuf, blog, v);
    softmax_o_kernel<<<dim3(36, BATCH), 128>>>(blog, cbuf);
    route_fused_kernel<1><<<dim3(100, BATCH), 256>>>(xhat, cbuf, blog, v);
    softmax_o_kernel<<<dim3(36, BATCH), 128>>>(blog, cbuf);
    route_fused_kernel<2><<<dim3(100, BATCH), 256>>>(xhat, cbuf, blog, v);

    // FC head (split-K + reduce)
    fc_part_kernel<<<dim3(64, 2, 4), 256>>>(v, fw1, partb, 1600, 4096, 400);
    fc_reduce_kernel<true><<<(128 * 4096 + 255) / 256, 256>>>(partb, fb1, f1, 4096, 4);
    fc_part_kernel<<<dim3(64, 2, 8), 256>>>(f1, fw2, partb, 4096, 4096, 512);
    fc_reduce_kernel<true><<<(128 * 4096 + 255) / 256, 256>>>(partb, fb2, f2, 4096, 8);
    fc_part_kernel<<<dim3(2, 2, 32), 256>>>(f2, fw3, partb, 4096, 100, 128);
    fc_reduce_kernel<false><<<(128 * 100 + 255) / 256, 256>>>(partb, fb3, outp, 100, 32);

    (void)in_sizes; (void)n_in; (void)out_size;
}